// round 2
// baseline (speedup 1.0000x reference)
#include <cuda_runtime.h>
#include <math.h>

// ---------------- problem constants ----------------
#define BATCH   4
#define SEQ     2048
#define DMODEL  1024
#define DSTATE  64
#define DINNER  2048            // EXPAND * DMODEL
#define TOK     (BATCH * SEQ)   // 8192
#define XZCOLS  (2 * DINNER)    // 4096
#define PROJ_N  (2 * DSTATE + 1) // 129
#define PROJ_LD 132             // padded stride for proj
#define CHUNK   64
#define NCHUNK  (SEQ / CHUNK)   // 32

// ---------------- scratch (device globals; no malloc allowed) ----------------
__device__ float g_xz[(size_t)TOK * XZCOLS];        // 128 MiB  [tok][4096]: xi | z
__device__ float g_proj[(size_t)TOK * PROJ_LD];     // ~4.3 MiB [tok][132]
__device__ float g_a[TOK];                          // per-token decay a_t
__device__ float g_aprod[BATCH * NCHUNK];           // per-chunk product of a
__device__ float g_B[(size_t)TOK * DINNER];         // 64 MiB (B, then y in-place)
__device__ float g_C[(size_t)TOK * DINNER];         // 64 MiB
__device__ float g_hend[BATCH * NCHUNK * DINNER];   // chunk-local scan end
__device__ float g_carry[BATCH * NCHUNK * DINNER];  // carry into each chunk

#define BM 128
#define BN 128
#define BK 16
#define TM 8
#define TN 8

// ---------------- fast SGEMM: all dims tile-multiples, 16B-aligned ----------------
__global__ __launch_bounds__(256)
void sgemm_fast(const float* __restrict__ A, int lda,
                const float* __restrict__ B, int ldb,
                float* __restrict__ C, int ldc, int K)
{
    __shared__ float As[BK][BM + 4];
    __shared__ float Bs[BK][BN + 4];

    const int tid  = threadIdx.x;
    const int tx   = tid & 15;
    const int ty   = tid >> 4;
    const int row0 = blockIdx.y * BM;
    const int col0 = blockIdx.x * BN;

    float acc[TM][TN];
#pragma unroll
    for (int i = 0; i < TM; i++)
#pragma unroll
        for (int j = 0; j < TN; j++) acc[i][j] = 0.f;

    for (int kk = 0; kk < K; kk += BK) {
        // A: 128x16 = 512 float4, 2 per thread, stored transposed As[k][m]
#pragma unroll
        for (int j = 0; j < 2; j++) {
            int linear = tid + 256 * j;
            int r  = linear >> 2;          // 0..127
            int kq = (linear & 3) * 4;     // 0,4,8,12
            float4 v = *(const float4*)&A[(size_t)(row0 + r) * lda + kk + kq];
            As[kq + 0][r] = v.x; As[kq + 1][r] = v.y;
            As[kq + 2][r] = v.z; As[kq + 3][r] = v.w;
        }
        // B: 16x128 = 512 float4, 2 per thread
#pragma unroll
        for (int j = 0; j < 2; j++) {
            int linear = tid + 256 * j;
            int k  = linear >> 5;          // 0..15
            int cq = (linear & 31) * 4;    // 0..124
            *(float4*)&Bs[k][cq] = *(const float4*)&B[(size_t)(kk + k) * ldb + col0 + cq];
        }
        __syncthreads();

#pragma unroll
        for (int k = 0; k < BK; k++) {
            float4 a0 = *(const float4*)&As[k][ty * 8];
            float4 a1 = *(const float4*)&As[k][ty * 8 + 4];
            float4 b0 = *(const float4*)&Bs[k][tx * 8];
            float4 b1 = *(const float4*)&Bs[k][tx * 8 + 4];
            float ra[8] = {a0.x, a0.y, a0.z, a0.w, a1.x, a1.y, a1.z, a1.w};
            float rb[8] = {b0.x, b0.y, b0.z, b0.w, b1.x, b1.y, b1.z, b1.w};
#pragma unroll
            for (int i = 0; i < TM; i++)
#pragma unroll
                for (int j = 0; j < TN; j++)
                    acc[i][j] = fmaf(ra[i], rb[j], acc[i][j]);
        }
        __syncthreads();
    }

#pragma unroll
    for (int i = 0; i < TM; i++) {
        int r = row0 + ty * TM + i;
        float4 v0 = make_float4(acc[i][0], acc[i][1], acc[i][2], acc[i][3]);
        float4 v1 = make_float4(acc[i][4], acc[i][5], acc[i][6], acc[i][7]);
        *(float4*)&C[(size_t)r * ldc + col0 + tx * 8]     = v0;
        *(float4*)&C[(size_t)r * ldc + col0 + tx * 8 + 4] = v1;
    }
}

// ---------------- guarded scalar SGEMM (odd shapes / unaligned A) ----------------
__global__ __launch_bounds__(256)
void sgemm_kernel(const float* __restrict__ A, int lda,
                  const float* __restrict__ B, int ldb,
                  float* __restrict__ C, int ldc,
                  int M, int N, int K)
{
    __shared__ float As[BK][BM + 4];
    __shared__ float Bs[BK][BN + 4];

    const int tid = threadIdx.x;
    const int tx  = tid & 15;
    const int ty  = tid >> 4;
    const int row0 = blockIdx.y * BM;
    const int col0 = blockIdx.x * BN;

    float acc[TM][TN];
#pragma unroll
    for (int i = 0; i < TM; i++)
#pragma unroll
        for (int j = 0; j < TN; j++) acc[i][j] = 0.f;

    const int a_k  = tid & 15;
    const int a_m0 = tid >> 4;
    const int b_n  = tid & 127;
    const int b_k0 = tid >> 7;

    for (int kk0 = 0; kk0 < K; kk0 += BK) {
#pragma unroll
        for (int i = 0; i < 8; i++) {
            int m = a_m0 + 16 * i;
            int gr = row0 + m;
            int gk = kk0 + a_k;
            As[a_k][m] = (gr < M && gk < K) ? A[(size_t)gr * lda + gk] : 0.f;
        }
#pragma unroll
        for (int i = 0; i < 8; i++) {
            int k = b_k0 + 2 * i;
            int gk = kk0 + k;
            int gc = col0 + b_n;
            Bs[k][b_n] = (gk < K && gc < N) ? B[(size_t)gk * ldb + gc] : 0.f;
        }
        __syncthreads();

#pragma unroll
        for (int k = 0; k < BK; k++) {
            float ra[TM], rb[TN];
#pragma unroll
            for (int i = 0; i < TM; i++) ra[i] = As[k][ty * TM + i];
#pragma unroll
            for (int j = 0; j < TN; j++) rb[j] = Bs[k][tx * TN + j];
#pragma unroll
            for (int i = 0; i < TM; i++)
#pragma unroll
                for (int j = 0; j < TN; j++)
                    acc[i][j] = fmaf(ra[i], rb[j], acc[i][j]);
        }
        __syncthreads();
    }

#pragma unroll
    for (int i = 0; i < TM; i++) {
        int r = row0 + ty * TM + i;
        if (r >= M) continue;
#pragma unroll
        for (int j = 0; j < TN; j++) {
            int c = col0 + tx * TN + j;
            if (c < N) C[(size_t)r * ldc + c] = acc[i][j];
        }
    }
}

// ---------------- per-token decay a_t = exp(A * softplus(proj[t,0])) ----------------
__global__ void compute_a_kernel(const float* __restrict__ A_log)
{
    int t = blockIdx.x * blockDim.x + threadIdx.x;
    if (t >= TOK) return;
    float x = g_proj[(size_t)t * PROJ_LD];
    float delta = (x > 20.f) ? x : log1pf(expf(x));
    float A = -expf(A_log[0]);
    g_a[t] = expf(A * delta);
}

// per-(batch,chunk) product of a over the chunk
__global__ void compute_aprod_kernel()
{
    int idx = blockIdx.x * blockDim.x + threadIdx.x;   // 0..127
    if (idx >= BATCH * NCHUNK) return;
    int n = idx / NCHUNK, ch = idx % NCHUNK;
    int tok0 = n * SEQ + ch * CHUNK;
    float p = 1.f;
#pragma unroll
    for (int i = 0; i < CHUNK; i++) p *= g_a[tok0 + i];
    g_aprod[idx] = p;
}

// ---------------- chunked scan pass 1: local scan ends ----------------
__global__ __launch_bounds__(256)
void scan_pass1_kernel()
{
    int c  = blockIdx.x * blockDim.x + threadIdx.x;  // channel 0..2047
    int ch = blockIdx.y;
    int n  = blockIdx.z;
    int tok0 = n * SEQ + ch * CHUNK;
    float h = 0.f;
    for (int i = 0; i < CHUNK; i++) {
        int tok = tok0 + i;
        float at = g_a[tok];
        float b  = g_B[(size_t)tok * DINNER + c] * g_xz[(size_t)tok * XZCOLS + c];
        h = at * h + b;
    }
    g_hend[(n * NCHUNK + ch) * DINNER + c] = h;
}

// ---------------- pass 2: chunk-level carries (32 sequential steps) ----------------
__global__ void scan_pass2_kernel()
{
    int idx = blockIdx.x * blockDim.x + threadIdx.x;  // 0..8191
    if (idx >= BATCH * DINNER) return;
    int n = idx / DINNER, c = idx % DINNER;
    float H = 0.f;
#pragma unroll
    for (int k = 0; k < NCHUNK; k++) {
        float he = g_hend[(n * NCHUNK + k) * DINNER + c];
        g_carry[(n * NCHUNK + k) * DINNER + c] = H;
        H = g_aprod[n * NCHUNK + k] * H + he;
    }
}

// ---------------- pass 3: rescan + fused pointwise; y written over g_B ----------------
__global__ __launch_bounds__(256)
void scan_pass3_kernel(const float* __restrict__ D)
{
    int c  = blockIdx.x * blockDim.x + threadIdx.x;
    int ch = blockIdx.y;
    int n  = blockIdx.z;
    int tok0 = n * SEQ + ch * CHUNK;
    float h = g_carry[(n * NCHUNK + ch) * DINNER + c];
    float Dv = D[c];
    for (int i = 0; i < CHUNK; i++) {
        int tok = tok0 + i;
        size_t bi = (size_t)tok * DINNER + c;
        float at = g_a[tok];
        float xi = g_xz[(size_t)tok * XZCOLS + c];
        float Bv = g_B[bi];
        h = at * h + Bv * xi;
        float z   = g_xz[(size_t)tok * XZCOLS + DINNER + c];
        float sig = 1.f / (1.f + expf(-z));
        g_B[bi] = (g_C[bi] * h + Dv * xi) * (z * sig);   // y in-place
    }
}

// ---------------- launch ----------------
static inline dim3 gemm_grid(int M, int N) {
    return dim3((N + BN - 1) / BN, (M + BM - 1) / BM, 1);
}

extern "C" void kernel_launch(void* const* d_in, const int* in_sizes, int n_in,
                              void* d_out, int out_size)
{
    const float* x     = (const float*)d_in[0];  // [4,2048,1024]
    const float* W_in  = (const float*)d_in[1];  // [1024,4096]
    const float* W_xp  = (const float*)d_in[2];  // [2048,129]
    const float* W_B   = (const float*)d_in[3];  // [64,2048]
    const float* W_C   = (const float*)d_in[4];  // [64,2048]
    const float* W_out = (const float*)d_in[5];  // [2048,1024]
    const float* D     = (const float*)d_in[6];  // [2048]
    const float* A_log = (const float*)d_in[7];  // [1]
    float* out = (float*)d_out;                  // [4,2048,1024]

    float* xz;   cudaGetSymbolAddress((void**)&xz,   g_xz);
    float* proj; cudaGetSymbolAddress((void**)&proj, g_proj);
    float* Bm;   cudaGetSymbolAddress((void**)&Bm,   g_B);
    float* Cm;   cudaGetSymbolAddress((void**)&Cm,   g_C);

    // 1) xz = x @ W_in            [8192,1024] x [1024,4096]  (fast path)
    sgemm_fast<<<gemm_grid(TOK, XZCOLS), 256>>>(x, DMODEL, W_in, XZCOLS,
                                                xz, XZCOLS, DMODEL);
    // 2) proj = xi @ W_xp         [8192,2048] x [2048,129]   (guarded)
    sgemm_kernel<<<gemm_grid(TOK, PROJ_N), 256>>>(xz, XZCOLS, W_xp, PROJ_N,
                                                  proj, PROJ_LD, TOK, PROJ_N, DINNER);
    // 3) a_t and chunk products
    compute_a_kernel<<<(TOK + 255) / 256, 256>>>(A_log);
    compute_aprod_kernel<<<1, 128>>>();
    // 4) B = B_raw @ W_B          [8192,64] x [64,2048]      (guarded: A unaligned)
    sgemm_kernel<<<gemm_grid(TOK, DINNER), 256>>>(proj + 1, PROJ_LD, W_B, DINNER,
                                                  Bm, DINNER, TOK, DINNER, DSTATE);
    // 5) C = C_raw @ W_C
    sgemm_kernel<<<gemm_grid(TOK, DINNER), 256>>>(proj + 1 + DSTATE, PROJ_LD, W_C, DINNER,
                                                  Cm, DINNER, TOK, DINNER, DSTATE);
    // 6-8) chunked scan + fused pointwise (y -> g_B in place)
    dim3 sgrid(DINNER / 256, NCHUNK, BATCH);
    scan_pass1_kernel<<<sgrid, 256>>>();
    scan_pass2_kernel<<<(BATCH * DINNER + 255) / 256, 256>>>();
    scan_pass3_kernel<<<sgrid, 256>>>(D);
    // 9) out = y @ W_out          [8192,2048] x [2048,1024]  (fast path)
    sgemm_fast<<<gemm_grid(TOK, DMODEL), 256>>>(Bm, DINNER, W_out, DMODEL,
                                                out, DMODEL, DINNER);
}

// round 8
// speedup vs baseline: 1.6816x; 1.6816x over previous
#include <cuda_runtime.h>
#include <cuda_bf16.h>
#include <math.h>
#include <stdint.h>

// ---------------- problem constants ----------------
#define BATCH   4
#define SEQ     2048
#define DMODEL  1024
#define DSTATE  64
#define DINNER  2048
#define TOK     (BATCH * SEQ)    // 8192
#define XZCOLS  (2 * DINNER)     // 4096
#define PROJ_N  (2 * DSTATE + 1) // 129
#define PROJ_LD 132
#define CHUNK   64
#define NCHUNK  (SEQ / CHUNK)    // 32

// ---------------- fp32 scratch ----------------
__device__ float g_xz[(size_t)TOK * XZCOLS];        // [tok][4096]: xi | z
__device__ float g_proj[(size_t)TOK * PROJ_LD];
__device__ float g_a[TOK];
__device__ float g_aprod[BATCH * NCHUNK];
__device__ float g_B[(size_t)TOK * DINNER];         // B, then y in place
__device__ float g_C[(size_t)TOK * DINNER];
__device__ float g_hend[BATCH * NCHUNK * DINNER];
__device__ float g_carry[BATCH * NCHUNK * DINNER];

// ---------------- bf16 split operand buffers ----------------
__device__ __nv_bfloat16 g_xhi[(size_t)TOK * DMODEL];
__device__ __nv_bfloat16 g_xlo[(size_t)TOK * DMODEL];
__device__ __nv_bfloat16 g_WinT_hi[(size_t)XZCOLS * DMODEL];
__device__ __nv_bfloat16 g_WinT_lo[(size_t)XZCOLS * DMODEL];
__device__ __nv_bfloat16 g_xihi[(size_t)TOK * DINNER];   // reused for y
__device__ __nv_bfloat16 g_xilo[(size_t)TOK * DINNER];
__device__ __nv_bfloat16 g_WxpT_hi[(size_t)PROJ_N * DINNER];
__device__ __nv_bfloat16 g_WxpT_lo[(size_t)PROJ_N * DINNER];
__device__ __nv_bfloat16 g_Brawhi[(size_t)TOK * DSTATE];
__device__ __nv_bfloat16 g_Brawlo[(size_t)TOK * DSTATE];
__device__ __nv_bfloat16 g_Crawhi[(size_t)TOK * DSTATE];
__device__ __nv_bfloat16 g_Crawlo[(size_t)TOK * DSTATE];
__device__ __nv_bfloat16 g_WBT_hi[(size_t)DINNER * DSTATE];
__device__ __nv_bfloat16 g_WBT_lo[(size_t)DINNER * DSTATE];
__device__ __nv_bfloat16 g_WCT_hi[(size_t)DINNER * DSTATE];
__device__ __nv_bfloat16 g_WCT_lo[(size_t)DINNER * DSTATE];
__device__ __nv_bfloat16 g_WoutT_hi[(size_t)DMODEL * DINNER];
__device__ __nv_bfloat16 g_WoutT_lo[(size_t)DMODEL * DINNER];

// ---------------- cp.async helpers (sm_80 PTX, valid on compute_103) ----------
__device__ __forceinline__ uint32_t smem_u32(const void* p) {
    uint32_t a;
    asm("{ .reg .u64 t; cvta.to.shared.u64 t, %1; cvt.u32.u64 %0, t; }" : "=r"(a) : "l"(p));
    return a;
}
__device__ __forceinline__ void cp_async16(uint32_t dst, const void* src) {
    asm volatile("cp.async.cg.shared.global [%0], [%1], 16;" :: "r"(dst), "l"(src));
}
__device__ __forceinline__ void cp_async16_pred(uint32_t dst, const void* src, int bytes) {
    asm volatile("cp.async.cg.shared.global [%0], [%1], 16, %2;"
                 :: "r"(dst), "l"(src), "r"(bytes));
}
#define CP_COMMIT() asm volatile("cp.async.commit_group;" ::: "memory")
#define CP_WAIT(n)  asm volatile("cp.async.wait_group %0;" :: "n"(n) : "memory")

__device__ __forceinline__ void mma_bf16(float& c0, float& c1, float& c2, float& c3,
                                         uint32_t a0, uint32_t a1, uint32_t a2, uint32_t a3,
                                         uint32_t b0, uint32_t b1) {
    asm volatile(
        "mma.sync.aligned.m16n8k16.row.col.f32.bf16.bf16.f32 "
        "{%0,%1,%2,%3}, {%4,%5,%6,%7}, {%8,%9}, {%0,%1,%2,%3};"
        : "+f"(c0), "+f"(c1), "+f"(c2), "+f"(c3)
        : "r"(a0), "r"(a1), "r"(a2), "r"(a3), "r"(b0), "r"(b1));
}

// ---------------- split-bf16 HMMA GEMM ----------------
// C[M,N] = A[M,K] @ W[K,N];  A as [M,K], B operand as [N,K] (both K-major bf16).
// 3 passes: Ahi*Bhi + Ahi*Blo + Alo*Bhi, fp32 accum in registers, C written once.
// CTA tile 128x128, warp tile 32x64 (4x2 warps), BK=32, cp.async double buffer.
#define SROW 40   // smem row stride in bf16 (80B: 16B-aligned, conflict-free LDS pattern)

__global__ __launch_bounds__(256)
void hgemm_kernel(const __nv_bfloat16* __restrict__ Ahi, const __nv_bfloat16* __restrict__ Alo,
                  const __nv_bfloat16* __restrict__ Bhi, const __nv_bfloat16* __restrict__ Blo,
                  float* __restrict__ C, int ldc, int Nact, int K)
{
    __shared__ __align__(16) __nv_bfloat16 As[2][128 * SROW];
    __shared__ __align__(16) __nv_bfloat16 Bs[2][128 * SROW];

    const int tid  = threadIdx.x;
    const int wid  = tid >> 5;
    const int lane = tid & 31;
    const int wm   = wid & 3;          // 4 warps along M
    const int wn   = wid >> 2;         // 2 warps along N
    const int g    = lane >> 2;        // group 0..7
    const int t    = lane & 3;         // tid-in-group
    const int row0 = blockIdx.y * 128;
    const int col0 = blockIdx.x * 128;

    float acc[2][8][4];
#pragma unroll
    for (int i = 0; i < 2; i++)
#pragma unroll
        for (int j = 0; j < 8; j++)
#pragma unroll
            for (int q = 0; q < 4; q++) acc[i][j][q] = 0.f;

    const int kcn = K / 32;
    const int nch = 3 * kcn;
    const __nv_bfloat16* pA[3] = {Ahi, Ahi, Alo};
    const __nv_bfloat16* pB[3] = {Bhi, Blo, Bhi};

    const int lr = tid >> 2;           // 0..63  (row index; rows r and r+64 per thread)
    const int lq = tid & 3;            // 16B chunk within 64B row

    auto issue_load = [&](int i, int stage) {
        const int p  = i / kcn;
        const int kc = i % kcn;
        const __nv_bfloat16* Ab = pA[p] + (size_t)row0 * K + kc * 32;
        const __nv_bfloat16* Bb = pB[p] + (size_t)col0 * K + kc * 32;
        uint32_t abase = smem_u32(&As[stage][0]);
        uint32_t bbase = smem_u32(&Bs[stage][0]);
#pragma unroll
        for (int j = 0; j < 2; j++) {
            int r = lr + j * 64;
            cp_async16(abase + (r * SROW + lq * 8) * 2,
                       (const char*)Ab + (size_t)r * K * 2 + lq * 16);
        }
#pragma unroll
        for (int j = 0; j < 2; j++) {
            int r = lr + j * 64;
            int valid = (col0 + r) < Nact;
            const char* src = (const char*)Bb + (size_t)(valid ? r : 0) * K * 2 + lq * 16;
            cp_async16_pred(bbase + (r * SROW + lq * 8) * 2, src, valid ? 16 : 0);
        }
    };

    issue_load(0, 0);
    CP_COMMIT();

    for (int i = 0; i < nch; i++) {
        const int st = i & 1;
        if (i + 1 < nch) {
            issue_load(i + 1, st ^ 1);
            CP_COMMIT();
            CP_WAIT(1);
        } else {
            CP_WAIT(0);
        }
        __syncthreads();

        const uint32_t* As32 = (const uint32_t*)&As[st][0];
        const uint32_t* Bs32 = (const uint32_t*)&Bs[st][0];
#pragma unroll
        for (int k16 = 0; k16 < 2; k16++) {
            const int kh = k16 * 8;    // u32 offset within row
            uint32_t a[2][4];
#pragma unroll
            for (int mt = 0; mt < 2; mt++) {
                int r = wm * 32 + mt * 16 + g;
                a[mt][0] = As32[r * (SROW / 2) + kh + t];
                a[mt][1] = As32[(r + 8) * (SROW / 2) + kh + t];
                a[mt][2] = As32[r * (SROW / 2) + kh + t + 4];
                a[mt][3] = As32[(r + 8) * (SROW / 2) + kh + t + 4];
            }
            uint32_t b[8][2];
#pragma unroll
            for (int nt = 0; nt < 8; nt++) {
                int r = wn * 64 + nt * 8 + g;
                b[nt][0] = Bs32[r * (SROW / 2) + kh + t];
                b[nt][1] = Bs32[r * (SROW / 2) + kh + t + 4];
            }
#pragma unroll
            for (int mt = 0; mt < 2; mt++)
#pragma unroll
                for (int nt = 0; nt < 8; nt++)
                    mma_bf16(acc[mt][nt][0], acc[mt][nt][1], acc[mt][nt][2], acc[mt][nt][3],
                             a[mt][0], a[mt][1], a[mt][2], a[mt][3],
                             b[nt][0], b[nt][1]);
        }
        __syncthreads();
    }

    // epilogue: c0,c1 -> (row, col..col+1); c2,c3 -> (row+8, ...)
#pragma unroll
    for (int mt = 0; mt < 2; mt++) {
        int r = row0 + wm * 32 + mt * 16 + g;
#pragma unroll
        for (int nt = 0; nt < 8; nt++) {
            int c = col0 + wn * 64 + nt * 8 + t * 2;
            if (c + 1 < Nact) {
                *(float2*)&C[(size_t)r * ldc + c] =
                    make_float2(acc[mt][nt][0], acc[mt][nt][1]);
                *(float2*)&C[(size_t)(r + 8) * ldc + c] =
                    make_float2(acc[mt][nt][2], acc[mt][nt][3]);
            } else if (c < Nact) {
                C[(size_t)r * ldc + c] = acc[mt][nt][0];
                C[(size_t)(r + 8) * ldc + c] = acc[mt][nt][2];
            }
        }
    }
}

// ---------------- conversion kernels ----------------
__device__ __forceinline__ void split2(float v, __nv_bfloat16* hi, __nv_bfloat16* lo, size_t i) {
    __nv_bfloat16 h = __float2bfloat16(v);
    hi[i] = h;
    lo[i] = __float2bfloat16(v - __bfloat162float(h));
}

__global__ void conv_split_kernel(const float* __restrict__ s,
                                  __nv_bfloat16* __restrict__ hi,
                                  __nv_bfloat16* __restrict__ lo, int n)
{
    int i = blockIdx.x * blockDim.x + threadIdx.x;
    if (i < n) split2(s[i], hi, lo, (size_t)i);
}

__global__ void conv_xi_kernel()
{
    int i = blockIdx.x * blockDim.x + threadIdx.x;
    if (i >= TOK * DINNER) return;
    int t = i >> 11, c = i & 2047;
    split2(g_xz[(size_t)t * XZCOLS + c], g_xihi, g_xilo, (size_t)i);
}

__global__ void conv_raw_kernel(int off, __nv_bfloat16* __restrict__ hi,
                                __nv_bfloat16* __restrict__ lo)
{
    int i = blockIdx.x * blockDim.x + threadIdx.x;
    if (i >= TOK * DSTATE) return;
    int t = i >> 6, j = i & 63;
    split2(g_proj[(size_t)t * PROJ_LD + off + j], hi, lo, (size_t)i);
}

// transpose + split: src [R,C] fp32 -> dst [C,R] bf16 hi/lo
__global__ void convT_kernel(const float* __restrict__ src, int R, int C,
                             __nv_bfloat16* __restrict__ dhi,
                             __nv_bfloat16* __restrict__ dlo)
{
    __shared__ float t[32][33];
    int c0 = blockIdx.x * 32, r0 = blockIdx.y * 32;
    int x = threadIdx.x, y = threadIdx.y;
#pragma unroll
    for (int j = 0; j < 32; j += 8) {
        int r = r0 + y + j, c = c0 + x;
        t[y + j][x] = (r < R && c < C) ? src[(size_t)r * C + c] : 0.f;
    }
    __syncthreads();
#pragma unroll
    for (int j = 0; j < 32; j += 8) {
        int c = c0 + y + j, r = r0 + x;
        if (c < C && r < R)
            split2(t[x][y + j], dhi, dlo, (size_t)c * R + r);
    }
}

// ---------------- scalar / scan kernels ----------------
__global__ void compute_a_kernel(const float* __restrict__ A_log)
{
    int t = blockIdx.x * blockDim.x + threadIdx.x;
    if (t >= TOK) return;
    float x = g_proj[(size_t)t * PROJ_LD];
    float delta = (x > 20.f) ? x : log1pf(expf(x));
    float A = -expf(A_log[0]);
    g_a[t] = expf(A * delta);
}

__global__ void compute_aprod_kernel()
{
    int idx = blockIdx.x * blockDim.x + threadIdx.x;
    if (idx >= BATCH * NCHUNK) return;
    int n = idx / NCHUNK, ch = idx % NCHUNK;
    int tok0 = n * SEQ + ch * CHUNK;
    float p = 1.f;
#pragma unroll
    for (int i = 0; i < CHUNK; i++) p *= g_a[tok0 + i];
    g_aprod[idx] = p;
}

__global__ __launch_bounds__(256)
void scan_pass1_kernel()
{
    int c  = blockIdx.x * blockDim.x + threadIdx.x;
    int ch = blockIdx.y;
    int n  = blockIdx.z;
    int tok0 = n * SEQ + ch * CHUNK;
    float h = 0.f;
    for (int i = 0; i < CHUNK; i++) {
        int tok = tok0 + i;
        float at = g_a[tok];
        float b  = g_B[(size_t)tok * DINNER + c] * g_xz[(size_t)tok * XZCOLS + c];
        h = at * h + b;
    }
    g_hend[(n * NCHUNK + ch) * DINNER + c] = h;
}

__global__ void scan_pass2_kernel()
{
    int idx = blockIdx.x * blockDim.x + threadIdx.x;
    if (idx >= BATCH * DINNER) return;
    int n = idx / DINNER, c = idx % DINNER;
    float H = 0.f;
#pragma unroll
    for (int k = 0; k < NCHUNK; k++) {
        float he = g_hend[(n * NCHUNK + k) * DINNER + c];
        g_carry[(n * NCHUNK + k) * DINNER + c] = H;
        H = g_aprod[n * NCHUNK + k] * H + he;
    }
}

__global__ __launch_bounds__(256)
void scan_pass3_kernel(const float* __restrict__ D)
{
    int c  = blockIdx.x * blockDim.x + threadIdx.x;
    int ch = blockIdx.y;
    int n  = blockIdx.z;
    int tok0 = n * SEQ + ch * CHUNK;
    float h = g_carry[(n * NCHUNK + ch) * DINNER + c];
    float Dv = D[c];
    for (int i = 0; i < CHUNK; i++) {
        int tok = tok0 + i;
        size_t bi = (size_t)tok * DINNER + c;
        float at = g_a[tok];
        float xi = g_xz[(size_t)tok * XZCOLS + c];
        float Bv = g_B[bi];
        h = at * h + Bv * xi;
        float z   = g_xz[(size_t)tok * XZCOLS + DINNER + c];
        float sig = 1.f / (1.f + expf(-z));
        g_B[bi] = (g_C[bi] * h + Dv * xi) * (z * sig);   // y in-place
    }
}

// ---------------- launch ----------------
template <typename T>
static T* sym(T* symbol) {
    void* p = nullptr;
    cudaGetSymbolAddress(&p, (const void*)symbol);
    return (T*)p;
}

extern "C" void kernel_launch(void* const* d_in, const int* in_sizes, int n_in,
                              void* d_out, int out_size)
{
    const float* x     = (const float*)d_in[0];
    const float* W_in  = (const float*)d_in[1];
    const float* W_xp  = (const float*)d_in[2];
    const float* W_B   = (const float*)d_in[3];
    const float* W_C   = (const float*)d_in[4];
    const float* W_out = (const float*)d_in[5];
    const float* D     = (const float*)d_in[6];
    const float* A_log = (const float*)d_in[7];
    float* out = (float*)d_out;

    float* xz   = sym(g_xz);
    float* proj = sym(g_proj);
    float* Bm   = sym(g_B);
    float* Cm   = sym(g_C);
    __nv_bfloat16 *xhi = sym(g_xhi), *xlo = sym(g_xlo);
    __nv_bfloat16 *winh = sym(g_WinT_hi), *winl = sym(g_WinT_lo);
    __nv_bfloat16 *xih = sym(g_xihi), *xil = sym(g_xilo);
    __nv_bfloat16 *wxh = sym(g_WxpT_hi), *wxl = sym(g_WxpT_lo);
    __nv_bfloat16 *brh = sym(g_Brawhi), *brl = sym(g_Brawlo);
    __nv_bfloat16 *crh = sym(g_Crawhi), *crl = sym(g_Crawlo);
    __nv_bfloat16 *wbh = sym(g_WBT_hi), *wbl = sym(g_WBT_lo);
    __nv_bfloat16 *wch = sym(g_WCT_hi), *wcl = sym(g_WCT_lo);
    __nv_bfloat16 *woh = sym(g_WoutT_hi), *wol = sym(g_WoutT_lo);

    // 1) operand prep + xz = x @ W_in
    conv_split_kernel<<<(TOK * DMODEL + 255) / 256, 256>>>(x, xhi, xlo, TOK * DMODEL);
    convT_kernel<<<dim3(XZCOLS / 32, DMODEL / 32), dim3(32, 8)>>>(W_in, DMODEL, XZCOLS, winh, winl);
    hgemm_kernel<<<dim3(XZCOLS / 128, TOK / 128), 256>>>(
        xhi, xlo, winh, winl, xz, XZCOLS, XZCOLS, DMODEL);

    // 2) proj = xi @ W_xp
    conv_xi_kernel<<<(TOK * DINNER + 255) / 256, 256>>>();
    convT_kernel<<<dim3((PROJ_N + 31) / 32, DINNER / 32), dim3(32, 8)>>>(W_xp, DINNER, PROJ_N, wxh, wxl);
    hgemm_kernel<<<dim3((PROJ_N + 127) / 128, TOK / 128), 256>>>(
        xih, xil, wxh, wxl, proj, PROJ_LD, PROJ_N, DINNER);

    // 3) decay terms
    compute_a_kernel<<<(TOK + 255) / 256, 256>>>(A_log);
    compute_aprod_kernel<<<1, 128>>>();

    // 4) B = B_raw @ W_B ; C = C_raw @ W_C   (K = 64)
    conv_raw_kernel<<<(TOK * DSTATE + 255) / 256, 256>>>(1, brh, brl);
    conv_raw_kernel<<<(TOK * DSTATE + 255) / 256, 256>>>(1 + DSTATE, crh, crl);
    convT_kernel<<<dim3(DINNER / 32, DSTATE / 32), dim3(32, 8)>>>(W_B, DSTATE, DINNER, wbh, wbl);
    convT_kernel<<<dim3(DINNER / 32, DSTATE / 32), dim3(32, 8)>>>(W_C, DSTATE, DINNER, wch, wcl);
    hgemm_kernel<<<dim3(DINNER / 128, TOK / 128), 256>>>(
        brh, brl, wbh, wbl, Bm, DINNER, DINNER, DSTATE);
    hgemm_kernel<<<dim3(DINNER / 128, TOK / 128), 256>>>(
        crh, crl, wch, wcl, Cm, DINNER, DINNER, DSTATE);

    // 5) chunked scan + fused pointwise (y -> g_B)
    dim3 sgrid(DINNER / 256, NCHUNK, BATCH);
    scan_pass1_kernel<<<sgrid, 256>>>();
    scan_pass2_kernel<<<(BATCH * DINNER + 255) / 256, 256>>>();
    scan_pass3_kernel<<<sgrid, 256>>>(D);

    // 6) out = y @ W_out
    conv_split_kernel<<<(TOK * DINNER + 255) / 256, 256>>>(Bm, xih, xil, TOK * DINNER);
    convT_kernel<<<dim3(DMODEL / 32, DINNER / 32), dim3(32, 8)>>>(W_out, DINNER, DMODEL, woh, wol);
    hgemm_kernel<<<dim3(DMODEL / 128, TOK / 128), 256>>>(
        xih, xil, woh, wol, out, DMODEL, DMODEL, DINNER);
}